// round 16
// baseline (speedup 1.0000x reference)
#include <cuda_runtime.h>
#include <cuda_fp16.h>
#include <cstdint>

// ---------------------------------------------------------------------------
// R16: M=32/warp (4 wm x 4 wn), TILE_E=128, 512 thr. B registers reused
//   across 2 M-tiles -> B wavefronts halved vs R15. Depth-4 B prefetch,
//   scalar prefetch, phase-scoped fragments (R15 machinery retained).
// ---------------------------------------------------------------------------

#define TILE_E 128
#define NTHR   512

__device__ __align__(16) uint32_t g_W1a[320*4*32*4];  // 163840
__device__ __align__(16) uint32_t g_W1b[320*4*32*2];  // 81920
__device__ __align__(16) uint32_t g_W2 [256*4*32*2];  // 65536

// ------------------------- smem layout (bytes) -----------------------------
#define OFF_S1   0        // 128 x 66 half   = 16896
#define OFF_S2   16896    // 128 x 72 half   = 18432
#define OFF_V1   35328    // 3x128 x 34 h    = 26112
#define OFF_V2   61440    // 3x128 x 40 h    = 30720  (ends 92160)
#define OFF_ZSG  92160    // 128 x 98 f32    = 50176
#define SMEM_BYTES 142336
#define OFF_ZV   0
#define P_ZV     34
#define OFF_WLS  61440
#define OFF_WLV  77824

#define P_S1 66
#define P_S2 72
#define P_V1 34
#define P_V2 40

// --------------------------- device helpers --------------------------------
__device__ __forceinline__ void ldm4(uint32_t r[4], const __half* p) {
    uint32_t a = (uint32_t)__cvta_generic_to_shared(p);
    asm volatile("ldmatrix.sync.aligned.m8n8.x4.shared.b16 {%0,%1,%2,%3}, [%4];"
                 : "=r"(r[0]), "=r"(r[1]), "=r"(r[2]), "=r"(r[3]) : "r"(a));
}
__device__ __forceinline__ void mma_f16(float c[4], const uint32_t a[4],
                                        uint32_t b0, uint32_t b1) {
    asm volatile("mma.sync.aligned.m16n8k16.row.col.f32.f16.f16.f32 "
                 "{%0,%1,%2,%3}, {%4,%5,%6,%7}, {%8,%9}, {%0,%1,%2,%3};"
                 : "+f"(c[0]), "+f"(c[1]), "+f"(c[2]), "+f"(c[3])
                 : "r"(a[0]), "r"(a[1]), "r"(a[2]), "r"(a[3]), "r"(b0), "r"(b1));
}
__device__ __forceinline__ uint32_t h2u(__half h) {
    __half2 t = __half2half2(h); return *reinterpret_cast<uint32_t*>(&t);
}
__device__ __forceinline__ uint32_t hmul2u(uint32_t x, uint32_t s) {
    __half2 c = __hmul2(*(__half2*)&x, *(__half2*)&s); return *(uint32_t*)&c;
}
__device__ __forceinline__ uint32_t hfma2u(uint32_t x, uint32_t s, uint32_t a) {
    __half2 c = __hfma2(*(__half2*)&x, *(__half2*)&s, *(__half2*)&a); return *(uint32_t*)&c;
}
__device__ __forceinline__ void loadB6(uint32_t d[6], const uint4* pa, const uint2* pb) {
    uint4 x = __ldg(pa);
    uint2 y = __ldg(pb);
    d[0]=x.x; d[1]=x.y; d[2]=x.z; d[3]=x.w; d[4]=y.x; d[5]=y.y;
}
__device__ __forceinline__ void loadB2(uint32_t d[2], const uint2* p) {
    uint2 x = __ldg(p);
    d[0]=x.x; d[1]=x.y;
}

// ---------------------------------------------------------------------------
// Weight prep: wn=4 slices.
//  W1a[((kt*4+wn)*32+lane)*4 + j]: j = nt*2+r (nt 0..1), n=(wn*3+nt)*8+lane/4
//  W1b[((kt*4+wn)*32+lane)*2 + r]: nt=2
//  W2 [((kt*4+wn)*32+lane)*2 + r]: n = wn*8+lane/4
//  k0 = kt*16 + (lane&3)*2 + r*8 -> half2{W[k0,n], W[k0+1,n]}
// ---------------------------------------------------------------------------
__device__ __forceinline__ float w1val(int k, int n,
    const float* wss_s, const float* wvv_s, const float* wss_g, const float* wvv_g) {
    const float A_SS = rsqrtf(8192.0f), A_VV = rsqrtf(6144.0f);
    if (k < 4096) {
        int u = k >> 6, v = k & 63;
        return (n < 64) ? A_SS * wss_s[(u * 64 + v) * 64 + n]
                        : A_SS * wss_g[(u * 64 + v) * 32 + (n - 64)];
    }
    int kk = k - 4096, u = kk >> 5, v = kk & 31;
    return (n < 64) ? A_VV * wvv_s[(u * 32 + v) * 64 + n]
                    : A_VV * wvv_g[(u * 32 + v) * 32 + (n - 64)];
}

__global__ void prep_kernel(const float* __restrict__ wss_s, const float* __restrict__ wvv_s,
                            const float* __restrict__ wss_g, const float* __restrict__ wvv_g,
                            const float* __restrict__ wsv_v, const float* __restrict__ wvs_v) {
    int t = blockIdx.x * blockDim.x + threadIdx.x;
    if (t < 320 * 4 * 32) {
        int lane = t & 31, wn = (t >> 5) & 3, kt = t >> 7;
        int nb = lane >> 2;
        int kb = kt * 16 + (lane & 3) * 2;
#pragma unroll
        for (int j = 0; j < 4; ++j) {
            int nt = j >> 1, r = j & 1;
            int n  = (wn * 3 + nt) * 8 + nb;
            int k0 = kb + r * 8;
            __half2 h = __floats2half2_rn(w1val(k0, n, wss_s, wvv_s, wss_g, wvv_g),
                                          w1val(k0 + 1, n, wss_s, wvv_s, wss_g, wvv_g));
            g_W1a[t * 4 + j] = *(uint32_t*)&h;
        }
#pragma unroll
        for (int r = 0; r < 2; ++r) {
            int n  = (wn * 3 + 2) * 8 + nb;
            int k0 = kb + r * 8;
            __half2 h = __floats2half2_rn(w1val(k0, n, wss_s, wvv_s, wss_g, wvv_g),
                                          w1val(k0 + 1, n, wss_s, wvv_s, wss_g, wvv_g));
            g_W1b[t * 2 + r] = *(uint32_t*)&h;
        }
    } else if (t < 320 * 4 * 32 + 256 * 4 * 32) {
        int t2 = t - 320 * 4 * 32;
        int lane = t2 & 31, wn = (t2 >> 5) & 3, kt = t2 >> 7;
        const float A_SV = rsqrtf(12288.0f);
        int n  = wn * 8 + (lane >> 2);
        int kb = kt * 16 + (lane & 3) * 2;
#pragma unroll
        for (int r = 0; r < 2; ++r) {
            float f[2];
#pragma unroll
            for (int q = 0; q < 2; ++q) {
                int k = kb + r * 8 + q;
                if (k < 2048) { int u = k >> 5, v = k & 31; f[q] = A_SV * wsv_v[(u * 32 + v) * 32 + n]; }
                else { int kk = k - 2048, u = kk >> 6, v = kk & 63; f[q] = A_SV * wvs_v[(u * 64 + v) * 32 + n]; }
            }
            __half2 h = __floats2half2_rn(f[0], f[1]);
            g_W2[t2 * 2 + r] = *(uint32_t*)&h;
        }
    }
}

// ---------------------------------------------------------------------------
// Main kernel: 512 threads (16 warps = 4 wm x 4 wn), 128 edges/CTA.
// ---------------------------------------------------------------------------
__global__ void __launch_bounds__(NTHR, 1)
main_kernel(const float* __restrict__ f1, const float* __restrict__ f2,
            const float* __restrict__ wl_s_g, const float* __restrict__ wl_v_g,
            float* __restrict__ out, int E) {
    extern __shared__ char sm[];
    __half* s1h = (__half*)(sm + OFF_S1);
    __half* s2h = (__half*)(sm + OFF_S2);
    __half* v1h = (__half*)(sm + OFF_V1);
    __half* v2h = (__half*)(sm + OFF_V2);
    float*  zsg = (float*)(sm + OFF_ZSG);
    float*  zv  = (float*)(sm + OFF_ZV);
    float*  wls = (float*)(sm + OFF_WLS);
    float*  wlv = (float*)(sm + OFF_WLV);

    const int tid  = threadIdx.x;
    const int warp = tid >> 5;
    const int lane = tid & 31;
    const int wm   = warp & 3;
    const int wn   = warp >> 2;     // 0..3
    const int e0   = blockIdx.x * TILE_E;

    // ---- stage inputs as fp16 (zero-padded past E) ----
    for (int idx = tid; idx < TILE_E * 160; idx += NTHR) {
        int e = idx / 160, c = idx - e * 160;
        float a = 0.f, b = 0.f;
        if (e0 + e < E) {
            a = f1[(size_t)(e0 + e) * 160 + c];
            b = f2[(size_t)(e0 + e) * 160 + c];
        }
        if (c < 64) {
            s1h[e * P_S1 + c] = __float2half_rn(a);
            s2h[e * P_S2 + c] = __float2half_rn(b);
        } else {
            int cc = c - 64, u = cc / 3, i = cc - u * 3;
            v1h[(i * TILE_E + e) * P_V1 + u] = __float2half_rn(a);
            v2h[(i * TILE_E + e) * P_V2 + u] = __float2half_rn(b);
        }
    }
    __syncthreads();

    const int r0 = wm * 32 + (lane >> 2);
    const __half* lm_s2 = s2h + (wm * 32 + (lane & 15)) * P_S2 + ((lane >> 4) << 3);
    const __half* lm_v2 = v2h + (wm * 32 + (lane & 15)) * P_V2 + ((lane >> 4) << 3);

    // =========================== GEMM1 ===========================
    const uint4* gBa = (const uint4*)g_W1a + (size_t)wn * 32 + lane;   // +128/kt
    const uint2* gBb = (const uint2*)g_W1b + (size_t)wn * 32 + lane;   // +128/kt
    float acc1[2][3][4];
#pragma unroll
    for (int t = 0; t < 2; ++t)
#pragma unroll
        for (int nt = 0; nt < 3; ++nt)
            acc1[t][nt][0] = acc1[t][nt][1] = acc1[t][nt][2] = acc1[t][nt][3] = 0.f;

    uint32_t Bst[4][6];
#pragma unroll
    for (int p = 0; p < 4; ++p)
        loadB6(Bst[p], gBa + (size_t)p * 128, gBb + (size_t)p * 128);

    // ---- ss phase (kt 0..255): fs2 live, scalars prefetched ----
    {
        uint32_t fs2[2][4][4];
#pragma unroll
        for (int t = 0; t < 2; ++t)
#pragma unroll
            for (int j = 0; j < 4; ++j)
                ldm4(fs2[t][j], lm_s2 + t * 16 * P_S2 + j * 16);

        uint32_t ha0 = h2u(s1h[r0 * P_S1]);
        uint32_t hb0 = h2u(s1h[(r0 + 8) * P_S1]);
        uint32_t ha1 = h2u(s1h[(r0 + 16) * P_S1]);
        uint32_t hb1 = h2u(s1h[(r0 + 24) * P_S1]);
        for (int c = 0; c < 64; ++c) {
            uint32_t na0 = ha0, nb0 = hb0, na1 = ha1, nb1 = hb1;
            if (c + 1 < 64) {
                na0 = h2u(s1h[r0 * P_S1 + c + 1]);
                nb0 = h2u(s1h[(r0 + 8) * P_S1 + c + 1]);
                na1 = h2u(s1h[(r0 + 16) * P_S1 + c + 1]);
                nb1 = h2u(s1h[(r0 + 24) * P_S1 + c + 1]);
            }
#pragma unroll
            for (int kl = 0; kl < 4; ++kl) {
                int kt = c * 4 + kl;
                uint32_t* B = Bst[kl];
                uint32_t a0[4], a1[4];
                a0[0] = hmul2u(fs2[0][kl][0], ha0); a0[1] = hmul2u(fs2[0][kl][1], hb0);
                a0[2] = hmul2u(fs2[0][kl][2], ha0); a0[3] = hmul2u(fs2[0][kl][3], hb0);
                a1[0] = hmul2u(fs2[1][kl][0], ha1); a1[1] = hmul2u(fs2[1][kl][1], hb1);
                a1[2] = hmul2u(fs2[1][kl][2], ha1); a1[3] = hmul2u(fs2[1][kl][3], hb1);
#pragma unroll
                for (int nt = 0; nt < 3; ++nt) {
                    mma_f16(acc1[0][nt], a0, B[2 * nt], B[2 * nt + 1]);
                    mma_f16(acc1[1][nt], a1, B[2 * nt], B[2 * nt + 1]);
                }
                int ktn = kt + 4;
                if (ktn < 320)
                    loadB6(B, gBa + (size_t)ktn * 128, gBb + (size_t)ktn * 128);
            }
            ha0 = na0; hb0 = nb0; ha1 = na1; hb1 = nb1;
        }
    }

    // ---- vv phase (kt 256..319): fv2 live ----
    {
        uint32_t fv2[2][3][2][4];
#pragma unroll
        for (int t = 0; t < 2; ++t)
#pragma unroll
            for (int i = 0; i < 3; ++i)
#pragma unroll
                for (int j = 0; j < 2; ++j)
                    ldm4(fv2[t][i][j], lm_v2 + i * (TILE_E * P_V2) + t * 16 * P_V2 + j * 16);

        for (int c = 64; c < 80; ++c) {
            int c2 = c - 64;
#pragma unroll
            for (int h = 0; h < 2; ++h) {
                int u = 2 * c2 + h;
                uint32_t ha[2][3], hb[2][3];
#pragma unroll
                for (int t = 0; t < 2; ++t)
#pragma unroll
                    for (int i = 0; i < 3; ++i) {
                        ha[t][i] = h2u(v1h[(i * TILE_E + r0 + t * 16) * P_V1 + u]);
                        hb[t][i] = h2u(v1h[(i * TILE_E + r0 + t * 16 + 8) * P_V1 + u]);
                    }
#pragma unroll
                for (int vb = 0; vb < 2; ++vb) {
                    int kt = c * 4 + h * 2 + vb;
                    uint32_t* B = Bst[h * 2 + vb];
                    uint32_t a0[4], a1[4];
#pragma unroll
                    for (int q = 0; q < 4; ++q) {
                        int sel = q & 1;
                        a0[q] = hmul2u(fv2[0][0][vb][q], sel ? hb[0][0] : ha[0][0]);
                        a1[q] = hmul2u(fv2[1][0][vb][q], sel ? hb[1][0] : ha[1][0]);
#pragma unroll
                        for (int i = 1; i < 3; ++i) {
                            a0[q] = hfma2u(fv2[0][i][vb][q], sel ? hb[0][i] : ha[0][i], a0[q]);
                            a1[q] = hfma2u(fv2[1][i][vb][q], sel ? hb[1][i] : ha[1][i], a1[q]);
                        }
                    }
#pragma unroll
                    for (int nt = 0; nt < 3; ++nt) {
                        mma_f16(acc1[0][nt], a0, B[2 * nt], B[2 * nt + 1]);
                        mma_f16(acc1[1][nt], a1, B[2 * nt], B[2 * nt + 1]);
                    }
                    int ktn = kt + 4;
                    if (ktn < 320)
                        loadB6(B, gBa + (size_t)ktn * 128, gBb + (size_t)ktn * 128);
                }
            }
        }
    }

    // z_sg writeback
    {
        int cb = (lane & 3) * 2;
#pragma unroll
        for (int t = 0; t < 2; ++t)
#pragma unroll
            for (int nt = 0; nt < 3; ++nt) {
                int col = (wn * 3 + nt) * 8 + cb;
                int row = r0 + t * 16;
                *(float2*)&zsg[row * 98 + col]       = make_float2(acc1[t][nt][0], acc1[t][nt][1]);
                *(float2*)&zsg[(row + 8) * 98 + col] = make_float2(acc1[t][nt][2], acc1[t][nt][3]);
            }
    }

    // =========================== GEMM2 ===========================
    const uint2* gB2 = (const uint2*)g_W2 + (size_t)wn * 32 + lane;    // +128/kt
    float acc2[2][3][4];
#pragma unroll
    for (int t = 0; t < 2; ++t)
#pragma unroll
        for (int i = 0; i < 3; ++i)
            acc2[t][i][0] = acc2[t][i][1] = acc2[t][i][2] = acc2[t][i][3] = 0.f;

    uint32_t Cst[4][2];
#pragma unroll
    for (int p = 0; p < 4; ++p) loadB2(Cst[p], gB2 + (size_t)p * 128);

    // ---- sv phase (kt 0..127): fv2 live, scalars prefetched ----
    {
        uint32_t fv2[2][3][2][4];
#pragma unroll
        for (int t = 0; t < 2; ++t)
#pragma unroll
            for (int i = 0; i < 3; ++i)
#pragma unroll
                for (int j = 0; j < 2; ++j)
                    ldm4(fv2[t][i][j], lm_v2 + i * (TILE_E * P_V2) + t * 16 * P_V2 + j * 16);

        uint32_t ha0 = h2u(s1h[r0 * P_S1]);
        uint32_t hb0 = h2u(s1h[(r0 + 8) * P_S1]);
        uint32_t ha1 = h2u(s1h[(r0 + 16) * P_S1]);
        uint32_t hb1 = h2u(s1h[(r0 + 24) * P_S1]);
        for (int c = 0; c < 16; ++c) {
#pragma unroll
            for (int uu = 0; uu < 4; ++uu) {
                int u = 4 * c + uu;
                uint32_t na0 = ha0, nb0 = hb0, na1 = ha1, nb1 = hb1;
                if (u + 1 < 64) {
                    na0 = h2u(s1h[r0 * P_S1 + u + 1]);
                    nb0 = h2u(s1h[(r0 + 8) * P_S1 + u + 1]);
                    na1 = h2u(s1h[(r0 + 16) * P_S1 + u + 1]);
                    nb1 = h2u(s1h[(r0 + 24) * P_S1 + u + 1]);
                }
#pragma unroll
                for (int vb = 0; vb < 2; ++vb) {
                    int kt = c * 8 + uu * 2 + vb;
                    uint32_t* C = Cst[(uu * 2 + vb) & 3];
#pragma unroll
                    for (int i = 0; i < 3; ++i) {
                        uint32_t a0[4], a1[4];
                        a0[0] = hmul2u(fv2[0][i][vb][0], ha0); a0[1] = hmul2u(fv2[0][i][vb][1], hb0);
                        a0[2] = hmul2u(fv2[0][i][vb][2], ha0); a0[3] = hmul2u(fv2[0][i][vb][3], hb0);
                        a1[0] = hmul2u(fv2[1][i][vb][0], ha1); a1[1] = hmul2u(fv2[1][i][vb][1], hb1);
                        a1[2] = hmul2u(fv2[1][i][vb][2], ha1); a1[3] = hmul2u(fv2[1][i][vb][3], hb1);
                        mma_f16(acc2[0][i], a0, C[0], C[1]);
                        mma_f16(acc2[1][i], a1, C[0], C[1]);
                    }
                    int ktn = kt + 4;
                    if (ktn < 256) loadB2(C, gB2 + (size_t)ktn * 128);
                }
                ha0 = na0; hb0 = nb0; ha1 = na1; hb1 = nb1;
            }
        }
    }

    // ---- vs phase (kt 128..255): fs2 reloaded ----
    {
        uint32_t fs2[2][4][4];
#pragma unroll
        for (int t = 0; t < 2; ++t)
#pragma unroll
            for (int j = 0; j < 4; ++j)
                ldm4(fs2[t][j], lm_s2 + t * 16 * P_S2 + j * 16);

        for (int c = 16; c < 32; ++c) {
            int c2 = c - 16;
#pragma unroll
            for (int h = 0; h < 2; ++h) {
                int u = 2 * c2 + h;
                uint32_t ha[2][3], hb[2][3];
#pragma unroll
                for (int t = 0; t < 2; ++t)
#pragma unroll
                    for (int i = 0; i < 3; ++i) {
                        ha[t][i] = h2u(v1h[(i * TILE_E + r0 + t * 16) * P_V1 + u]);
                        hb[t][i] = h2u(v1h[(i * TILE_E + r0 + t * 16 + 8) * P_V1 + u]);
                    }
#pragma unroll
                for (int vb = 0; vb < 4; ++vb) {
                    int kt = c * 8 + h * 4 + vb;
                    uint32_t* C = Cst[vb];
#pragma unroll
                    for (int i = 0; i < 3; ++i) {
                        uint32_t a0[4], a1[4];
                        a0[0] = hmul2u(fs2[0][vb][0], ha[0][i]); a0[1] = hmul2u(fs2[0][vb][1], hb[0][i]);
                        a0[2] = hmul2u(fs2[0][vb][2], ha[0][i]); a0[3] = hmul2u(fs2[0][vb][3], hb[0][i]);
                        a1[0] = hmul2u(fs2[1][vb][0], ha[1][i]); a1[1] = hmul2u(fs2[1][vb][1], hb[1][i]);
                        a1[2] = hmul2u(fs2[1][vb][2], ha[1][i]); a1[3] = hmul2u(fs2[1][vb][3], hb[1][i]);
                        mma_f16(acc2[0][i], a0, C[0], C[1]);
                        mma_f16(acc2[1][i], a1, C[0], C[1]);
                    }
                    int ktn = kt + 4;
                    if (ktn < 256) loadB2(C, gB2 + (size_t)ktn * 128);
                }
            }
        }
    }

    __syncthreads();   // all GEMM smem reads done; inputs dead

    // z_v writeback (aliases input head; pitch 34 even -> float2-safe)
    {
        int cb = (lane & 3) * 2;
#pragma unroll
        for (int t = 0; t < 2; ++t)
#pragma unroll
            for (int i = 0; i < 3; ++i) {
                int row = i * TILE_E + r0 + t * 16;
                int col = wn * 8 + cb;
                *(float2*)&zv[row * P_ZV + col]       = make_float2(acc2[t][i][0], acc2[t][i][1]);
                *(float2*)&zv[(row + 8) * P_ZV + col] = make_float2(acc2[t][i][2], acc2[t][i][3]);
            }
    }
    // epilogue weights into dead v2h region
    for (int idx = tid; idx < 4096; idx += NTHR) wls[idx] = wl_s_g[idx];
    for (int idx = tid; idx < 1024; idx += NTHR) wlv[idx] = wl_v_g[idx];

    // activations on z_sg
    for (int idx = tid; idx < TILE_E * 96; idx += NTHR) {
        int e = idx / 96, cc = idx - e * 96;
        float v = zsg[e * 98 + cc];
        float sg = 1.f / (1.f + __expf(-v));
        zsg[e * 98 + cc] = (cc < 64) ? v * sg : sg;
    }
    __syncthreads();

    // gate z_v
    for (int idx = tid; idx < 384 * 32; idx += NTHR) {
        int row = idx >> 5, v = idx & 31;
        int e = row & 127;
        zv[row * P_ZV + v] *= zsg[e * 98 + 64 + v];
    }
    __syncthreads();

    // s_out = silu(z_s) @ wl_s / 8
    {
        int e = tid >> 2, wbase = (tid & 3) * 16;
        bool valid = (e0 + e) < E;
#pragma unroll
        for (int wb = 0; wb < 16; wb += 8) {
            float a[8];
#pragma unroll
            for (int j = 0; j < 8; ++j) a[j] = 0.f;
            for (int u = 0; u < 64; ++u) {
                float zs = zsg[e * 98 + u];
                float4 w0 = *(const float4*)&wls[u * 64 + wbase + wb];
                float4 w1 = *(const float4*)&wls[u * 64 + wbase + wb + 4];
                a[0] += zs * w0.x; a[1] += zs * w0.y; a[2] += zs * w0.z; a[3] += zs * w0.w;
                a[4] += zs * w1.x; a[5] += zs * w1.y; a[6] += zs * w1.z; a[7] += zs * w1.w;
            }
            if (valid) {
                float4 o0 = make_float4(a[0]*0.125f, a[1]*0.125f, a[2]*0.125f, a[3]*0.125f);
                float4 o1 = make_float4(a[4]*0.125f, a[5]*0.125f, a[6]*0.125f, a[7]*0.125f);
                *(float4*)&out[(size_t)(e0 + e) * 160 + wbase + wb]     = o0;
                *(float4*)&out[(size_t)(e0 + e) * 160 + wbase + wb + 4] = o1;
            }
        }
    }
    // v_out = (g*z_v) @ wl_v / sqrt(32)
    const float R32 = 0.17677669529663687f;
    for (int r = tid; r < 384; r += NTHR) {
        int i = r >> 7, e = r & 127;
        float acc[32];
#pragma unroll
        for (int w = 0; w < 32; ++w) acc[w] = 0.f;
        for (int v = 0; v < 32; ++v) {
            float zval = zv[r * P_ZV + v];
#pragma unroll
            for (int w4 = 0; w4 < 32; w4 += 4) {
                float4 wv = *(const float4*)&wlv[v * 32 + w4];
                acc[w4]   += zval * wv.x; acc[w4+1] += zval * wv.y;
                acc[w4+2] += zval * wv.z; acc[w4+3] += zval * wv.w;
            }
        }
        if (e0 + e < E) {
#pragma unroll
            for (int w = 0; w < 32; ++w)
                out[(size_t)(e0 + e) * 160 + 64 + w * 3 + i] = acc[w] * R32;
        }
    }
}

// ---------------------------------------------------------------------------
extern "C" void kernel_launch(void* const* d_in, const int* in_sizes, int n_in,
                              void* d_out, int out_size) {
    const float* f1    = (const float*)d_in[0];
    const float* f2    = (const float*)d_in[1];
    const float* wss_s = (const float*)d_in[4];
    const float* wvv_s = (const float*)d_in[5];
    const float* wss_g = (const float*)d_in[6];
    const float* wvv_g = (const float*)d_in[7];
    const float* wsv_v = (const float*)d_in[8];
    const float* wvs_v = (const float*)d_in[9];
    const float* wl_s  = (const float*)d_in[10];
    const float* wl_v  = (const float*)d_in[11];
    float* out = (float*)d_out;
    int E = in_sizes[0] / 160;

    prep_kernel<<<288, 256>>>(wss_s, wvv_s, wss_g, wvv_g, wsv_v, wvs_v);
    cudaFuncSetAttribute(main_kernel, cudaFuncAttributeMaxDynamicSharedMemorySize, SMEM_BYTES);
    int ntiles = (E + TILE_E - 1) / TILE_E;
    main_kernel<<<ntiles, NTHR, SMEM_BYTES>>>(f1, f2, wl_s, wl_v, out, E);
}

// round 17
// speedup vs baseline: 1.0853x; 1.0853x over previous
#include <cuda_runtime.h>
#include <cuda_fp16.h>
#include <cstdint>

// ---------------------------------------------------------------------------
// R17: R15 (best, 715us) + scalar prefetch in vv/vs phases + warp-convergence
//   barriers so wm-peer warps share L1-resident B lines. No structural change.
// ---------------------------------------------------------------------------

#define TILE_E 128
#define NTHR   512

__device__ __align__(16) uint32_t g_W1[320*2*3*128];   // 245760
__device__ __align__(16) uint32_t g_W2[256*2*128];     // 65536

// ------------------------- smem layout (bytes) -----------------------------
#define OFF_S1   0        // 128 x 66 half   = 16896
#define OFF_S2   16896    // 128 x 72 half   = 18432
#define OFF_V1   35328    // 3x128 x 34 h    = 26112
#define OFF_V2   61440    // 3x128 x 40 h    = 30720  (ends 92160)
#define OFF_ZSG  92160    // 128 x 98 f32    = 50176
#define SMEM_BYTES 142336
#define OFF_ZV   0
#define P_ZV     34
#define OFF_WLS  61440
#define OFF_WLV  77824

#define P_S1 66
#define P_S2 72
#define P_V1 34
#define P_V2 40

// --------------------------- device helpers --------------------------------
__device__ __forceinline__ void ldm4(uint32_t r[4], const __half* p) {
    uint32_t a = (uint32_t)__cvta_generic_to_shared(p);
    asm volatile("ldmatrix.sync.aligned.m8n8.x4.shared.b16 {%0,%1,%2,%3}, [%4];"
                 : "=r"(r[0]), "=r"(r[1]), "=r"(r[2]), "=r"(r[3]) : "r"(a));
}
__device__ __forceinline__ void mma_f16(float c[4], const uint32_t a[4],
                                        uint32_t b0, uint32_t b1) {
    asm volatile("mma.sync.aligned.m16n8k16.row.col.f32.f16.f16.f32 "
                 "{%0,%1,%2,%3}, {%4,%5,%6,%7}, {%8,%9}, {%0,%1,%2,%3};"
                 : "+f"(c[0]), "+f"(c[1]), "+f"(c[2]), "+f"(c[3])
                 : "r"(a[0]), "r"(a[1]), "r"(a[2]), "r"(a[3]), "r"(b0), "r"(b1));
}
__device__ __forceinline__ uint32_t h2u(__half h) {
    __half2 t = __half2half2(h); return *reinterpret_cast<uint32_t*>(&t);
}
__device__ __forceinline__ uint32_t hmul2u(uint32_t x, uint32_t s) {
    __half2 c = __hmul2(*(__half2*)&x, *(__half2*)&s); return *(uint32_t*)&c;
}
__device__ __forceinline__ uint32_t hfma2u(uint32_t x, uint32_t s, uint32_t a) {
    __half2 c = __hfma2(*(__half2*)&x, *(__half2*)&s, *(__half2*)&a); return *(uint32_t*)&c;
}
__device__ __forceinline__ void loadB12(uint32_t d[12], const uint4* p) {
    uint4 x0 = __ldg(p);
    uint4 x1 = __ldg(p + 32);
    uint4 x2 = __ldg(p + 64);
    d[0]=x0.x; d[1]=x0.y; d[2]=x0.z;  d[3]=x0.w;
    d[4]=x1.x; d[5]=x1.y; d[6]=x1.z;  d[7]=x1.w;
    d[8]=x2.x; d[9]=x2.y; d[10]=x2.z; d[11]=x2.w;
}
__device__ __forceinline__ void loadB4(uint32_t d[4], const uint4* p) {
    uint4 x0 = __ldg(p);
    d[0]=x0.x; d[1]=x0.y; d[2]=x0.z; d[3]=x0.w;
}

// ---------------------------------------------------------------------------
// Weight prep (identical to R8/R15 packing).
// ---------------------------------------------------------------------------
__global__ void prep_kernel(const float* __restrict__ wss_s, const float* __restrict__ wvv_s,
                            const float* __restrict__ wss_g, const float* __restrict__ wvv_g,
                            const float* __restrict__ wsv_v, const float* __restrict__ wvs_v) {
    int t = blockIdx.x * blockDim.x + threadIdx.x;
    const float A_SS = rsqrtf(8192.0f);
    const float A_VV = rsqrtf(6144.0f);
    const float A_SV = rsqrtf(12288.0f);

    if (t < 320 * 2 * 3 * 32) {
        int lane = t & 31;
        int g    = (t >> 5) % 3;
        int wn   = (t / 96) & 1;
        int kt   = t / 192;
#pragma unroll
        for (int j = 0; j < 4; ++j) {
            int flatr = g * 4 + j;
            int nt = wn * 6 + (flatr >> 1);
            int r  = flatr & 1;
            int n  = nt * 8 + (lane >> 2);
            float f[2];
#pragma unroll
            for (int q = 0; q < 2; ++q) {
                int k = kt * 16 + (lane & 3) * 2 + r * 8 + q;
                float val;
                if (k < 4096) {
                    int u = k >> 6, v = k & 63;
                    val = (n < 64) ? A_SS * wss_s[(u * 64 + v) * 64 + n]
                                   : A_SS * wss_g[(u * 64 + v) * 32 + (n - 64)];
                } else {
                    int kk = k - 4096, u = kk >> 5, v = kk & 31;
                    val = (n < 64) ? A_VV * wvv_s[(u * 32 + v) * 64 + n]
                                   : A_VV * wvv_g[(u * 32 + v) * 32 + (n - 64)];
                }
                f[q] = val;
            }
            __half2 h = __floats2half2_rn(f[0], f[1]);
            g_W1[((kt * 2 + wn) * 3 + g) * 128 + lane * 4 + j] = *(uint32_t*)&h;
        }
    } else if (t < 320 * 2 * 3 * 32 + 256 * 2 * 32) {
        int t2 = t - 320 * 2 * 3 * 32;
        int lane = t2 & 31;
        int wn   = (t2 >> 5) & 1;
        int kt   = t2 >> 6;
#pragma unroll
        for (int j = 0; j < 4; ++j) {
            int nt = wn * 2 + (j >> 1);
            int r  = j & 1;
            int n  = nt * 8 + (lane >> 2);
            float f[2];
#pragma unroll
            for (int q = 0; q < 2; ++q) {
                int k = kt * 16 + (lane & 3) * 2 + r * 8 + q;
                float val;
                if (k < 2048) { int u = k >> 5, v = k & 31; val = A_SV * wsv_v[(u * 32 + v) * 32 + n]; }
                else { int kk = k - 2048, u = kk >> 6, v = kk & 63; val = A_SV * wvs_v[(u * 64 + v) * 32 + n]; }
                f[q] = val;
            }
            __half2 h = __floats2half2_rn(f[0], f[1]);
            g_W2[(kt * 2 + wn) * 128 + lane * 4 + j] = *(uint32_t*)&h;
        }
    }
}

// ---------------------------------------------------------------------------
// Main kernel: 512 threads (16 warps = 8 wm x 2 wn), 128 edges/CTA.
// ---------------------------------------------------------------------------
__global__ void __launch_bounds__(NTHR, 1)
main_kernel(const float* __restrict__ f1, const float* __restrict__ f2,
            const float* __restrict__ wl_s_g, const float* __restrict__ wl_v_g,
            float* __restrict__ out, int E) {
    extern __shared__ char sm[];
    __half* s1h = (__half*)(sm + OFF_S1);
    __half* s2h = (__half*)(sm + OFF_S2);
    __half* v1h = (__half*)(sm + OFF_V1);
    __half* v2h = (__half*)(sm + OFF_V2);
    float*  zsg = (float*)(sm + OFF_ZSG);
    float*  zv  = (float*)(sm + OFF_ZV);
    float*  wls = (float*)(sm + OFF_WLS);
    float*  wlv = (float*)(sm + OFF_WLV);

    const int tid  = threadIdx.x;
    const int warp = tid >> 5;
    const int lane = tid & 31;
    const int wm   = warp & 7;
    const int wn   = warp >> 3;
    const int e0   = blockIdx.x * TILE_E;

    // ---- stage inputs as fp16 (zero-padded past E) ----
    for (int idx = tid; idx < TILE_E * 160; idx += NTHR) {
        int e = idx / 160, c = idx - e * 160;
        float a = 0.f, b = 0.f;
        if (e0 + e < E) {
            a = f1[(size_t)(e0 + e) * 160 + c];
            b = f2[(size_t)(e0 + e) * 160 + c];
        }
        if (c < 64) {
            s1h[e * P_S1 + c] = __float2half_rn(a);
            s2h[e * P_S2 + c] = __float2half_rn(b);
        } else {
            int cc = c - 64, u = cc / 3, i = cc - u * 3;
            v1h[(i * TILE_E + e) * P_V1 + u] = __float2half_rn(a);
            v2h[(i * TILE_E + e) * P_V2 + u] = __float2half_rn(b);
        }
    }
    __syncthreads();

    const int r0 = wm * 16 + (lane >> 2);
    const __half* lm_s2 = s2h + (wm * 16 + (lane & 15)) * P_S2 + ((lane >> 4) << 3);
    const __half* lm_v2 = v2h + (wm * 16 + (lane & 15)) * P_V2 + ((lane >> 4) << 3);

    // =========================== GEMM1 ===========================
    const uint4* gB1 = (const uint4*)g_W1 + (size_t)wn * 96 + lane;
    float acc1[6][4];
#pragma unroll
    for (int nt = 0; nt < 6; ++nt)
        acc1[nt][0] = acc1[nt][1] = acc1[nt][2] = acc1[nt][3] = 0.f;

    uint32_t Bst[4][12];
#pragma unroll
    for (int p = 0; p < 4; ++p) loadB12(Bst[p], gB1 + (size_t)p * 192);

    // ---- ss phase (kt 0..255): fs2 live, scalars prefetched ----
    {
        uint32_t fs2[4][4];
#pragma unroll
        for (int j = 0; j < 4; ++j) ldm4(fs2[j], lm_s2 + j * 16);

        uint32_t ha = h2u(s1h[r0 * P_S1]);
        uint32_t hb = h2u(s1h[(r0 + 8) * P_S1]);
        for (int c = 0; c < 64; ++c) {
            if ((c & 15) == 0 && c) __syncthreads();   // convergence barrier
            uint32_t han = ha, hbn = hb;
            if (c + 1 < 64) {
                han = h2u(s1h[r0 * P_S1 + c + 1]);
                hbn = h2u(s1h[(r0 + 8) * P_S1 + c + 1]);
            }
#pragma unroll
            for (int kl = 0; kl < 4; ++kl) {
                int kt = c * 4 + kl;
                uint32_t* B = Bst[kl];
                uint32_t a[4];
                a[0] = hmul2u(fs2[kl][0], ha); a[1] = hmul2u(fs2[kl][1], hb);
                a[2] = hmul2u(fs2[kl][2], ha); a[3] = hmul2u(fs2[kl][3], hb);
#pragma unroll
                for (int nt = 0; nt < 6; ++nt)
                    mma_f16(acc1[nt], a, B[2 * nt], B[2 * nt + 1]);
                int ktn = kt + 4;
                if (ktn < 320) loadB12(B, gB1 + (size_t)ktn * 192);
            }
            ha = han; hb = hbn;
        }
    }

    // ---- vv phase (kt 256..319): fv2 live, scalars prefetched ----
    {
        uint32_t fv2[3][2][4];
#pragma unroll
        for (int i = 0; i < 3; ++i)
#pragma unroll
            for (int j = 0; j < 2; ++j)
                ldm4(fv2[i][j], lm_v2 + i * (TILE_E * P_V2) + j * 16);

        uint32_t ha[3], hb[3];
#pragma unroll
        for (int i = 0; i < 3; ++i) {
            ha[i] = h2u(v1h[(i * TILE_E + r0) * P_V1]);
            hb[i] = h2u(v1h[(i * TILE_E + r0 + 8) * P_V1]);
        }
        for (int c = 64; c < 80; ++c) {
            int c2 = c - 64;
#pragma unroll
            for (int h = 0; h < 2; ++h) {
                int u = 2 * c2 + h;
                uint32_t nha[3], nhb[3];
                int un = u + 1;
                if (un < 32) {
#pragma unroll
                    for (int i = 0; i < 3; ++i) {
                        nha[i] = h2u(v1h[(i * TILE_E + r0) * P_V1 + un]);
                        nhb[i] = h2u(v1h[(i * TILE_E + r0 + 8) * P_V1 + un]);
                    }
                } else {
#pragma unroll
                    for (int i = 0; i < 3; ++i) { nha[i] = ha[i]; nhb[i] = hb[i]; }
                }
#pragma unroll
                for (int vb = 0; vb < 2; ++vb) {
                    int kt = c * 4 + h * 2 + vb;
                    uint32_t* B = Bst[h * 2 + vb];
                    uint32_t a[4];
                    a[0] = hmul2u(fv2[0][vb][0], ha[0]);
                    a[1] = hmul2u(fv2[0][vb][1], hb[0]);
                    a[2] = hmul2u(fv2[0][vb][2], ha[0]);
                    a[3] = hmul2u(fv2[0][vb][3], hb[0]);
#pragma unroll
                    for (int i = 1; i < 3; ++i) {
                        a[0] = hfma2u(fv2[i][vb][0], ha[i], a[0]);
                        a[1] = hfma2u(fv2[i][vb][1], hb[i], a[1]);
                        a[2] = hfma2u(fv2[i][vb][2], ha[i], a[2]);
                        a[3] = hfma2u(fv2[i][vb][3], hb[i], a[3]);
                    }
#pragma unroll
                    for (int nt = 0; nt < 6; ++nt)
                        mma_f16(acc1[nt], a, B[2 * nt], B[2 * nt + 1]);
                    int ktn = kt + 4;
                    if (ktn < 320) loadB12(B, gB1 + (size_t)ktn * 192);
                }
#pragma unroll
                for (int i = 0; i < 3; ++i) { ha[i] = nha[i]; hb[i] = nhb[i]; }
            }
        }
    }

    // z_sg writeback (separate region; no barrier needed)
    {
        int cb = (lane & 3) * 2;
#pragma unroll
        for (int nt = 0; nt < 6; ++nt) {
            int col = (wn * 6 + nt) * 8 + cb;
            *(float2*)&zsg[r0 * 98 + col]       = make_float2(acc1[nt][0], acc1[nt][1]);
            *(float2*)&zsg[(r0 + 8) * 98 + col] = make_float2(acc1[nt][2], acc1[nt][3]);
        }
    }

    // =========================== GEMM2 ===========================
    const uint4* gB2 = (const uint4*)g_W2 + (size_t)wn * 32 + lane;
    float acc2[3][2][4];
#pragma unroll
    for (int i = 0; i < 3; ++i)
#pragma unroll
        for (int nt = 0; nt < 2; ++nt)
            acc2[i][nt][0] = acc2[i][nt][1] = acc2[i][nt][2] = acc2[i][nt][3] = 0.f;

    uint32_t Cst[4][4];
#pragma unroll
    for (int p = 0; p < 4; ++p) loadB4(Cst[p], gB2 + (size_t)p * 64);

    // ---- sv phase (kt 0..127): fv2 live, scalars prefetched ----
    {
        uint32_t fv2[3][2][4];
#pragma unroll
        for (int i = 0; i < 3; ++i)
#pragma unroll
            for (int j = 0; j < 2; ++j)
                ldm4(fv2[i][j], lm_v2 + i * (TILE_E * P_V2) + j * 16);

        uint32_t ha = h2u(s1h[r0 * P_S1]);
        uint32_t hb = h2u(s1h[(r0 + 8) * P_S1]);
        for (int c = 0; c < 16; ++c) {
            if (c == 8) __syncthreads();    // convergence barrier
#pragma unroll
            for (int uu = 0; uu < 4; ++uu) {
                int u = 4 * c + uu;
                uint32_t han = ha, hbn = hb;
                if (u + 1 < 64) {
                    han = h2u(s1h[r0 * P_S1 + u + 1]);
                    hbn = h2u(s1h[(r0 + 8) * P_S1 + u + 1]);
                }
#pragma unroll
                for (int vb = 0; vb < 2; ++vb) {
                    int kt = c * 8 + uu * 2 + vb;
                    uint32_t* C = Cst[(uu * 2 + vb) & 3];
                    uint32_t ai[3][4];
#pragma unroll
                    for (int i = 0; i < 3; ++i) {
                        ai[i][0] = hmul2u(fv2[i][vb][0], ha);
                        ai[i][1] = hmul2u(fv2[i][vb][1], hb);
                        ai[i][2] = hmul2u(fv2[i][vb][2], ha);
                        ai[i][3] = hmul2u(fv2[i][vb][3], hb);
                    }
#pragma unroll
                    for (int nt = 0; nt < 2; ++nt) {
#pragma unroll
                        for (int i = 0; i < 3; ++i)
                            mma_f16(acc2[i][nt], ai[i], C[2 * nt], C[2 * nt + 1]);
                    }
                    int ktn = kt + 4;
                    if (ktn < 256) loadB4(C, gB2 + (size_t)ktn * 64);
                }
                ha = han; hb = hbn;
            }
        }
    }

    // ---- vs phase (kt 128..255): fs2 reloaded, scalars prefetched ----
    {
        uint32_t fs2[4][4];
#pragma unroll
        for (int j = 0; j < 4; ++j) ldm4(fs2[j], lm_s2 + j * 16);

        uint32_t ha[3], hb[3];
#pragma unroll
        for (int i = 0; i < 3; ++i) {
            ha[i] = h2u(v1h[(i * TILE_E + r0) * P_V1]);
            hb[i] = h2u(v1h[(i * TILE_E + r0 + 8) * P_V1]);
        }
        for (int c = 16; c < 32; ++c) {
            if (c == 24) __syncthreads();   // convergence barrier
            int c2 = c - 16;
#pragma unroll
            for (int h = 0; h < 2; ++h) {
                int u = 2 * c2 + h;
                uint32_t nha[3], nhb[3];
                int un = u + 1;
                if (un < 32) {
#pragma unroll
                    for (int i = 0; i < 3; ++i) {
                        nha[i] = h2u(v1h[(i * TILE_E + r0) * P_V1 + un]);
                        nhb[i] = h2u(v1h[(i * TILE_E + r0 + 8) * P_V1 + un]);
                    }
                } else {
#pragma unroll
                    for (int i = 0; i < 3; ++i) { nha[i] = ha[i]; nhb[i] = hb[i]; }
                }
#pragma unroll
                for (int vb = 0; vb < 4; ++vb) {
                    int kt = c * 8 + h * 4 + vb;
                    uint32_t* C = Cst[vb];
                    uint32_t ai[3][4];
#pragma unroll
                    for (int i = 0; i < 3; ++i) {
                        ai[i][0] = hmul2u(fs2[vb][0], ha[i]);
                        ai[i][1] = hmul2u(fs2[vb][1], hb[i]);
                        ai[i][2] = hmul2u(fs2[vb][2], ha[i]);
                        ai[i][3] = hmul2u(fs2[vb][3], hb[i]);
                    }
#pragma unroll
                    for (int nt = 0; nt < 2; ++nt) {
#pragma unroll
                        for (int i = 0; i < 3; ++i)
                            mma_f16(acc2[i][nt], ai[i], C[2 * nt], C[2 * nt + 1]);
                    }
                    int ktn = kt + 4;
                    if (ktn < 256) loadB4(C, gB2 + (size_t)ktn * 64);
                }
#pragma unroll
                for (int i = 0; i < 3; ++i) { ha[i] = nha[i]; hb[i] = nhb[i]; }
            }
        }
    }

    __syncthreads();   // all GEMM smem reads done; inputs dead

    // z_v writeback (aliases input head; pitch 34 even -> float2-safe)
    {
        int cb = (lane & 3) * 2;
#pragma unroll
        for (int i = 0; i < 3; ++i)
#pragma unroll
            for (int nt = 0; nt < 2; ++nt) {
                int row = i * TILE_E + r0;
                int col = (wn * 2 + nt) * 8 + cb;
                *(float2*)&zv[row * P_ZV + col]       = make_float2(acc2[i][nt][0], acc2[i][nt][1]);
                *(float2*)&zv[(row + 8) * P_ZV + col] = make_float2(acc2[i][nt][2], acc2[i][nt][3]);
            }
    }
    // epilogue weights into dead v2h region
    for (int idx = tid; idx < 4096; idx += NTHR) wls[idx] = wl_s_g[idx];
    for (int idx = tid; idx < 1024; idx += NTHR) wlv[idx] = wl_v_g[idx];

    // activations on z_sg
    for (int idx = tid; idx < TILE_E * 96; idx += NTHR) {
        int e = idx / 96, cc = idx - e * 96;
        float v = zsg[e * 98 + cc];
        float sg = 1.f / (1.f + __expf(-v));
        zsg[e * 98 + cc] = (cc < 64) ? v * sg : sg;
    }
    __syncthreads();

    // gate z_v
    for (int idx = tid; idx < 384 * 32; idx += NTHR) {
        int row = idx >> 5, v = idx & 31;
        int e = row & 127;
        zv[row * P_ZV + v] *= zsg[e * 98 + 64 + v];
    }
    __syncthreads();

    // s_out = silu(z_s) @ wl_s / 8
    {
        int e = tid >> 2, wbase = (tid & 3) * 16;
        bool valid = (e0 + e) < E;
#pragma unroll
        for (int wb = 0; wb < 16; wb += 8) {
            float a[8];
#pragma unroll
            for (int j = 0; j < 8; ++j) a[j] = 0.f;
            for (int u = 0; u < 64; ++u) {
                float zs = zsg[e * 98 + u];
                float4 w0 = *(const float4*)&wls[u * 64 + wbase + wb];
                float4 w1 = *(const float4*)&wls[u * 64 + wbase + wb + 4];
                a[0] += zs * w0.x; a[1] += zs * w0.y; a[2] += zs * w0.z; a[3] += zs * w0.w;
                a[4] += zs * w1.x; a[5] += zs * w1.y; a[6] += zs * w1.z; a[7] += zs * w1.w;
            }
            if (valid) {
                float4 o0 = make_float4(a[0]*0.125f, a[1]*0.125f, a[2]*0.125f, a[3]*0.125f);
                float4 o1 = make_float4(a[4]*0.125f, a[5]*0.125f, a[6]*0.125f, a[7]*0.125f);
                *(float4*)&out[(size_t)(e0 + e) * 160 + wbase + wb]     = o0;
                *(float4*)&out[(size_t)(e0 + e) * 160 + wbase + wb + 4] = o1;
            }
        }
    }
    // v_out = (g*z_v) @ wl_v / sqrt(32)
    const float R32 = 0.17677669529663687f;
    for (int r = tid; r < 384; r += NTHR) {
        int i = r >> 7, e = r & 127;
        float acc[32];
#pragma unroll
        for (int w = 0; w < 32; ++w) acc[w] = 0.f;
        for (int v = 0; v < 32; ++v) {
            float zval = zv[r * P_ZV + v];
#pragma unroll
            for (int w4 = 0; w4 < 32; w4 += 4) {
                float4 wv = *(const float4*)&wlv[v * 32 + w4];
                acc[w4]   += zval * wv.x; acc[w4+1] += zval * wv.y;
                acc[w4+2] += zval * wv.z; acc[w4+3] += zval * wv.w;
            }
        }
        if (e0 + e < E) {
#pragma unroll
            for (int w = 0; w < 32; ++w)
                out[(size_t)(e0 + e) * 160 + 64 + w * 3 + i] = acc[w] * R32;
        }
    }
}

// ---------------------------------------------------------------------------
extern "C" void kernel_launch(void* const* d_in, const int* in_sizes, int n_in,
                              void* d_out, int out_size) {
    const float* f1    = (const float*)d_in[0];
    const float* f2    = (const float*)d_in[1];
    const float* wss_s = (const float*)d_in[4];
    const float* wvv_s = (const float*)d_in[5];
    const float* wss_g = (const float*)d_in[6];
    const float* wvv_g = (const float*)d_in[7];
    const float* wsv_v = (const float*)d_in[8];
    const float* wvs_v = (const float*)d_in[9];
    const float* wl_s  = (const float*)d_in[10];
    const float* wl_v  = (const float*)d_in[11];
    float* out = (float*)d_out;
    int E = in_sizes[0] / 160;

    prep_kernel<<<304, 256>>>(wss_s, wvv_s, wss_g, wvv_g, wsv_v, wvs_v);
    cudaFuncSetAttribute(main_kernel, cudaFuncAttributeMaxDynamicSharedMemorySize, SMEM_BYTES);
    int ntiles = (E + TILE_E - 1) / TILE_E;
    main_kernel<<<ntiles, NTHR, SMEM_BYTES>>>(f1, f2, wl_s, wl_v, out, E);
}